// round 11
// baseline (speedup 1.0000x reference)
#include <cuda_runtime.h>
#include <cuda_fp16.h>

#define S 160
#define SS (S*S)
#define S3 (S*S*S)
#define DG 96
#define DG2 (DG*DG)
#define DG3 (DG*DG*DG)
#define IMG_H 240
#define IMG_W 320
#define NVIEW 3
#define NSTEP 64
#define CLAMP_HI 158.999f          // f32(160 - 1.001)
#define NBLK 900                   // march blocks (10 x 30 x 3)

// 8-corner packed resized SDF (minus TRUNC), fp16:
//  g_sdf8[(x*S+y)*S+z] = uint4 of 4 half2:
//    .x=(x0,y0,z/z+1)  .y=(x0,y1,z/z+1)  .z=(x1,y0,z/z+1)  .w=(x1,y1,z/z+1)
__device__ uint4 g_sdf8[S3];       // 64 MB
__device__ float g_L[S*S*DG];      // intermediate xy-bilerped lines, 9.8 MB
__device__ float g_psum[NBLK];
__device__ int   g_pcnt[NBLK];
__device__ int   g_count;          // zero-initialized; reset after use

union HU { __half2 h; unsigned u; };

// ---------------------------------------------------------------------------
// Kernel 1a: xy-bilerp of source SDF at resized (i,j) for all source z.
// grid S*S, block 96. L[i][j][z] = bilerp - TRUNC.
// ---------------------------------------------------------------------------
__global__ __launch_bounds__(96) void resizeA_kernel(const float* __restrict__ sdf) {
    int b = blockIdx.x;            // S*S
    int i = b / S, j = b % S;
    int z = threadIdx.x;           // 96

    float cx = (i * 95.0f) / 159.0f;
    int x0 = (int)cx; float fx = cx - (float)x0; int x1 = min(x0 + 1, DG - 1);
    float cy = (j * 95.0f) / 159.0f;
    int y0 = (int)cy; float fy = cy - (float)y0; int y1 = min(y0 + 1, DG - 1);

    int base = (x0 * DG + y0) * DG + z;
    int xs = (x1 - x0) * DG2;
    int ys = (y1 - y0) * DG;
    float gxf = 1.0f - fx, gyf = 1.0f - fy;

    float v = __ldg(sdf + base) * (gxf * gyf) + __ldg(sdf + base + ys) * (gxf * fy)
            + __ldg(sdf + base + xs) * (fx * gyf) + __ldg(sdf + base + xs + ys) * (fx * fy);
    g_L[b * DG + z] = v - 1.5f;
}

// ---------------------------------------------------------------------------
// Kernel 1b: z-lerp 4 neighbor lines -> pack 8 fp16 corners per voxel.
// grid S*S, block 160.
// ---------------------------------------------------------------------------
__global__ __launch_bounds__(160) void resizeB_kernel() {
    int b = blockIdx.x;            // S*S
    int i = b / S, j = b % S;
    int i2 = min(i + 1, S - 1), j2 = min(j + 1, S - 1);
    int t = threadIdx.x;           // 160

    __shared__ float L[4][DG];
    const float* src0 = g_L + (i  * S + j ) * DG;
    const float* src1 = g_L + (i  * S + j2) * DG;
    const float* src2 = g_L + (i2 * S + j ) * DG;
    const float* src3 = g_L + (i2 * S + j2) * DG;
    for (int q = t; q < 4 * DG; q += 160) {
        int c = q / DG, z = q - c * DG;
        const float* s = (c == 0) ? src0 : (c == 1) ? src1 : (c == 2) ? src2 : src3;
        L[c][z] = __ldg(s + z);
    }
    __syncthreads();

    // z-lerp at output z = t
    float czf = (t * 95.0f) / 159.0f;
    int z0 = (int)czf; float fz = czf - (float)z0; int z1 = min(z0 + 1, DG - 1);
    // z-lerp at output z = t+1 (t=159 entry unused by march)
    int t1 = min(t + 1, S - 1);
    float czg = (t1 * 95.0f) / 159.0f;
    int w0 = (int)czg; float fw = czg - (float)w0; int w1 = min(w0 + 1, DG - 1);

    HU p00, p01, p10, p11;
    p00.h = __floats2half2_rn(fmaf(fz, L[0][z1] - L[0][z0], L[0][z0]),
                              fmaf(fw, L[0][w1] - L[0][w0], L[0][w0]));
    p01.h = __floats2half2_rn(fmaf(fz, L[1][z1] - L[1][z0], L[1][z0]),
                              fmaf(fw, L[1][w1] - L[1][w0], L[1][w0]));
    p10.h = __floats2half2_rn(fmaf(fz, L[2][z1] - L[2][z0], L[2][z0]),
                              fmaf(fw, L[2][w1] - L[2][w0], L[2][w0]));
    p11.h = __floats2half2_rn(fmaf(fz, L[3][z1] - L[3][z0], L[3][z0]),
                              fmaf(fw, L[3][w1] - L[3][w0], L[3][w0]));

    uint4 o; o.x = p00.u; o.y = p01.u; o.z = p10.u; o.w = p11.u;
    g_sdf8[b * S + t] = o;
}

// ---------------------------------------------------------------------------
// SDF sample: ONE 16B load, 8 fp16 corners, fp32 trilerp
// ---------------------------------------------------------------------------
__device__ __forceinline__ float sdf_sample8(int x0, int y0, int z0,
                                             float fx, float fy, float fz) {
    uint4 q = __ldg(g_sdf8 + ((x0 * S + y0) * S + z0));
    HU u;
    u.u = q.x; float2 c00 = __half22float2(u.h);
    u.u = q.y; float2 c01 = __half22float2(u.h);
    u.u = q.z; float2 c10 = __half22float2(u.h);
    u.u = q.w; float2 c11 = __half22float2(u.h);
    float v00 = fmaf(fz, c00.y - c00.x, c00.x);
    float v01 = fmaf(fz, c01.y - c01.x, c01.x);
    float v10 = fmaf(fz, c10.y - c10.x, c10.x);
    float v11 = fmaf(fz, c11.y - c11.x, c11.x);
    float v0 = fmaf(fy, v01 - v00, v00);
    float v1 = fmaf(fy, v11 - v10, v10);
    return fmaf(fx, v1 - v0, v0);
}

// 3-level separable weights for resized-trilerp-of-source-trilerp along one axis
__device__ __forceinline__ void axis_w(int c0, float f, float* W, int* g) {
    float cc0 = (c0 * 95.0f) / 159.0f;
    int b0 = (int)cc0; float f0 = cc0 - (float)b0;
    float cc1 = ((c0 + 1) * 95.0f) / 159.0f;
    int b1 = (int)cc1; float f1 = cc1 - (float)b1;
    int l = b1 - b0;                    // 0 or 1
    float g0 = 1.0f - f;
    float wa = f * (1.0f - f1), wb = f * f1;
    W[0] = g0 * (1.0f - f0) + (l == 0 ? wa : 0.0f);
    W[1] = g0 * f0 + (l == 0 ? wb : wa);
    W[2] = (l == 0 ? 0.0f : wb);
    g[0] = b0;
    g[1] = min(b0 + 1, DG - 1);
    g[2] = min(b0 + 2, DG - 1);
}

__device__ __forceinline__ float gather27(const float* __restrict__ src,
                                          const int* gx, const int* gy, const int* gz,
                                          const float* Wx, const float* Wy, const float* Wz) {
    float acc = 0.0f;
#pragma unroll
    for (int ia = 0; ia < 3; ia++) {
        float accy = 0.0f;
#pragma unroll
        for (int ib = 0; ib < 3; ib++) {
            const float* rr = src + (gx[ia] * DG + gy[ib]) * DG;
            float accz = __ldg(rr + gz[0]) * Wz[0]
                       + __ldg(rr + gz[1]) * Wz[1]
                       + __ldg(rr + gz[2]) * Wz[2];
            accy = fmaf(Wy[ib], accz, accy);
        }
        acc = fmaf(Wx[ia], accy, acc);
    }
    return acc;
}

// ---------------------------------------------------------------------------
// Kernel 2: fused march + shade + loss. grid (10, 30, 3), block 256.
// ---------------------------------------------------------------------------
__global__ __launch_bounds__(256) void march_kernel(
        const float* __restrict__ rgb,
        const float* __restrict__ sem,
        const float* __restrict__ poses,
        const float* __restrict__ views,
        float* __restrict__ out) {
    int tid = threadIdx.x;
    int warp = tid >> 5, lane = tid & 31;
    int wx = warp & 3, wy = warp >> 2;
    int lx = lane & 7, ly = lane >> 3;
    int w = blockIdx.x * 32 + wx * 8 + lx;
    int h = blockIdx.y * 8 + wy * 4 + ly;
    int v = blockIdx.z;

    const float offx[3] = {0.0f, 36.0f, 40.0f};
    const float offz[3] = {0.0f, 44.0f, 23.0f};
    const float* M = poses + v * 16;
    float ox = M[3]  / 0.0301f + offx[v];
    float oy = M[7]  / 0.0301f;
    float oz = M[11] / 0.0301f + offz[v];
    float uu = ((float)w - 160.0f) / 277.0f;
    float vv = ((float)h - 120.0f) / 277.0f;
    float dx = M[0] * uu + M[1] * vv + M[2];
    float dy = M[4] * uu + M[5] * vv + M[6];
    float dz = M[8] * uu + M[9] * vv + M[10];
    float nrm = sqrtf(dx * dx + dy * dy + dz * dz);
    dx /= nrm; dy /= nrm; dz /= nrm;

    float t = 0.0f;
    bool alive = true;
#pragma unroll 1
    for (int it = 0; it < NSTEP; ++it) {
        if (alive) {
            float px = fmaf(t, dx, ox);
            float py = fmaf(t, dy, oy);
            float pz = fmaf(t, dz, oz);
            bool dead = (px < 0.0f && dx <= 0.0f) || (px > 159.0f && dx >= 0.0f)
                     || (py < 0.0f && dy <= 0.0f) || (py > 159.0f && dy >= 0.0f)
                     || (pz < 0.0f && dz <= 0.0f) || (pz > 159.0f && dz >= 0.0f);
            if (dead) {
                alive = false;
            } else {
                float cx = fminf(fmaxf(px, 0.0f), CLAMP_HI);
                float cy = fminf(fmaxf(py, 0.0f), CLAMP_HI);
                float cz = fminf(fmaxf(pz, 0.0f), CLAMP_HI);
                int x0 = (int)cx, y0 = (int)cy, z0 = (int)cz;
                float s = sdf_sample8(x0, y0, z0,
                                      cx - (float)x0, cy - (float)y0, cz - (float)z0);
                t = fmaf(fmaxf(s, 0.25f), 2.0f, t);
            }
        }
        if (__all_sync(0xffffffffu, !alive)) break;
    }

    float contrib = 0.0f;
    int cnt = 0;
    if (alive) {
        float px = fmaf(t, dx, ox);
        float py = fmaf(t, dy, oy);
        float pz = fmaf(t, dz, oz);
        float cx = fminf(fmaxf(px, 0.0f), CLAMP_HI);
        float cy = fminf(fmaxf(py, 0.0f), CLAMP_HI);
        float cz = fminf(fmaxf(pz, 0.0f), CLAMP_HI);
        int x0 = (int)cx, y0 = (int)cy, z0 = (int)cz;
        float fx = cx - (float)x0, fy = cy - (float)y0, fz = cz - (float)z0;

        float s = sdf_sample8(x0, y0, z0, fx, fy, fz);

        bool inside = (px >= 0.0f) && (px <= 159.0f)
                   && (py >= 0.0f) && (py <= 159.0f)
                   && (pz >= 0.0f) && (pz <= 159.0f);
        bool valid = inside && (fabsf(s) < 1.0f);

        if (valid) {
            float Wx[3], Wy[3], Wz[3];
            int gx[3], gy[3], gz[3];
            axis_w(x0, fx, Wx, gx);
            axis_w(y0, fy, Wy, gy);
            axis_w(z0, fz, Wz, gz);

            float c0 = gather27(rgb,           gx, gy, gz, Wx, Wy, Wz);
            float c1 = gather27(rgb + DG3,     gx, gy, gz, Wx, Wy, Wz);
            float c2 = gather27(rgb + 2 * DG3, gx, gy, gz, Wx, Wy, Wz);

            int nx0 = min((int)(x0 * 0.6f), DG - 1);
            int nx1 = min((int)((x0 + 1) * 0.6f), DG - 1);
            int ny0 = min((int)(y0 * 0.6f), DG - 1);
            int ny1 = min((int)((y0 + 1) * 0.6f), DG - 1);
            int nz0 = min((int)(z0 * 0.6f), DG - 1);
            int nz1 = min((int)((z0 + 1) * 0.6f), DG - 1);
            float gxf = 1.0f - fx, gyf = 1.0f - fy, gzf = 1.0f - fz;
            const float* s00 = sem + (nx0 * DG + ny0) * DG;
            const float* s01 = sem + (nx0 * DG + ny1) * DG;
            const float* s10 = sem + (nx1 * DG + ny0) * DG;
            const float* s11 = sem + (nx1 * DG + ny1) * DG;
            float wv = gxf * gyf * (gzf * __ldg(s00 + nz0) + fz * __ldg(s00 + nz1))
                     + gxf * fy  * (gzf * __ldg(s01 + nz0) + fz * __ldg(s01 + nz1))
                     + fx  * gyf * (gzf * __ldg(s10 + nz0) + fz * __ldg(s10 + nz1))
                     + fx  * fy  * (gzf * __ldg(s11 + nz0) + fz * __ldg(s11 + nz1));

            const float* vw = views + ((size_t)(v * IMG_H + h) * IMG_W + w) * 3;
            contrib = (fabsf(c0 - vw[0]) + fabsf(c1 - vw[1]) + fabsf(c2 - vw[2])) * wv;
            cnt = 1;
        }
    }

    // deterministic block reduction + last-block finish
    __shared__ float ssum[256];
    __shared__ int scnt[256];
    ssum[tid] = contrib;
    scnt[tid] = cnt;
    __syncthreads();
#pragma unroll
    for (int o = 128; o > 0; o >>= 1) {
        if (tid < o) {
            ssum[tid] += ssum[tid + o];
            scnt[tid] += scnt[tid + o];
        }
        __syncthreads();
    }
    int bid = (blockIdx.z * gridDim.y + blockIdx.y) * gridDim.x + blockIdx.x;
    __shared__ bool amLast;
    if (tid == 0) {
        g_psum[bid] = ssum[0];
        g_pcnt[bid] = scnt[0];
        __threadfence();
        int tk = atomicAdd(&g_count, 1);
        amLast = (tk == NBLK - 1);
    }
    __syncthreads();

    if (amLast) {
        float sacc = 0.0f; int cacc = 0;
        for (int k = tid; k < NBLK; k += 256) {
            sacc += g_psum[k];
            cacc += g_pcnt[k];
        }
        ssum[tid] = sacc;
        scnt[tid] = cacc;
        __syncthreads();
#pragma unroll
        for (int o = 128; o > 0; o >>= 1) {
            if (tid < o) {
                ssum[tid] += ssum[tid + o];
                scnt[tid] += scnt[tid + o];
            }
            __syncthreads();
        }
        if (tid == 0) {
            float nv = 3.0f * (float)scnt[0];
            out[0] = 8.0f * ssum[0] / fmaxf(nv, 1.0f);
            g_count = 0;
        }
    }
}

// ---------------------------------------------------------------------------
extern "C" void kernel_launch(void* const* d_in, const int* in_sizes, int n_in,
                              void* d_out, int out_size) {
    const float* sdf   = (const float*)d_in[0];
    const float* rgb   = (const float*)d_in[1];
    const float* sem   = (const float*)d_in[2];
    const float* poses = (const float*)d_in[3];
    const float* views = (const float*)d_in[4];

    resizeA_kernel<<<S * S, 96>>>(sdf);
    resizeB_kernel<<<S * S, 160>>>();
    dim3 mg(IMG_W / 32, IMG_H / 8, NVIEW);
    march_kernel<<<mg, 256>>>(rgb, sem, poses, views, (float*)d_out);
}

// round 12
// speedup vs baseline: 1.1774x; 1.1774x over previous
#include <cuda_runtime.h>
#include <cuda_fp16.h>

#define S 160
#define SS (S*S)
#define S3 (S*S*S)
#define DG 96
#define DG2 (DG*DG)
#define DG3 (DG*DG*DG)
#define IMG_H 240
#define IMG_W 320
#define NVIEW 3
#define NPIX (NVIEW*IMG_H*IMG_W)   // 230400
#define NSTEP 64
#define CLAMP_HI 158.999f          // f32(160 - 1.001)
#define NBLK 900

// packed resized SDF, half precision:
//   g_sdfh[(x*S+y)*S+z] = float2 whose bits are two __half2:
//     .x bits = (S[y][z], S[y][z+1])   .y bits = (S[y+1][z], S[y+1][z+1])
__device__ float2 g_sdfh[S3];      // 32 MB
__device__ float  g_tbuf[NPIX];    // final ray parameter t
__device__ float  g_psum[NBLK];
__device__ int    g_pcnt[NBLK];
__device__ int    g_count;         // zero-initialized; reset after use

union HF { __half2 h; float f; };

// ---------------------------------------------------------------------------
// Kernel 1: separable SDF resize 96^3 -> 160^3 (minus TRUNC), packed half4.
// (R7 version: measured ~20us)
// ---------------------------------------------------------------------------
__global__ __launch_bounds__(192) void resize_sdf_kernel(const float* __restrict__ sdf) {
    int b = blockIdx.x;            // S*S
    int i = b / S, j = b % S;
    int t = threadIdx.x;           // 192

    float cx = (i * 95.0f) / 159.0f;
    int x0 = (int)cx; float fx = cx - (float)x0; int x1 = min(x0 + 1, DG - 1);

    __shared__ float ls[2][96];

    {
        int row = t >= 96;                       // 0 -> j, 1 -> j+1
        int z = t - row * 96;                    // 0..95
        int jj = row ? min(j + 1, S - 1) : j;
        float cy = (jj * 95.0f) / 159.0f;
        int y0 = (int)cy; float fy = cy - (float)y0; int y1 = min(y0 + 1, DG - 1);
        int base = (x0 * DG + y0) * DG + z;
        int xs = (x1 - x0) * DG2;
        int ys = (y1 - y0) * DG;
        float gxf = 1.0f - fx, gyf = 1.0f - fy;
        ls[row][z] = __ldg(sdf + base) * (gxf * gyf) + __ldg(sdf + base + ys) * (gxf * fy)
                   + __ldg(sdf + base + xs) * (fx * gyf) + __ldg(sdf + base + xs + ys) * (fx * fy);
    }
    __syncthreads();

    if (t < S) {
        float czf = (t * 95.0f) / 159.0f;
        int z0 = (int)czf; float fz = czf - (float)z0; int z1 = min(z0 + 1, DG - 1);
        float vA0 = fmaf(fz, ls[0][z1] - ls[0][z0], ls[0][z0]) - 1.5f;
        float vB0 = fmaf(fz, ls[1][z1] - ls[1][z0], ls[1][z0]) - 1.5f;

        int t1 = min(t + 1, S - 1);
        float czg = (t1 * 95.0f) / 159.0f;
        int w0 = (int)czg; float fw = czg - (float)w0; int w1 = min(w0 + 1, DG - 1);
        float vA1 = fmaf(fw, ls[0][w1] - ls[0][w0], ls[0][w0]) - 1.5f;
        float vB1 = fmaf(fw, ls[1][w1] - ls[1][w0], ls[1][w0]) - 1.5f;

        HF lo, hi;
        lo.h = __floats2half2_rn(vA0, vA1);
        hi.h = __floats2half2_rn(vB0, vB1);
        g_sdfh[(i * S + j) * S + t] = make_float2(lo.f, hi.f);
    }
}

// ---------------------------------------------------------------------------
// half4 SDF sample: 2x 8B loads, fp32 lerp
// ---------------------------------------------------------------------------
__device__ __forceinline__ float sdf_sample_h(int x0, int y0, int z0,
                                              float fx, float fy, float fz) {
    const float2* p = g_sdfh + ((x0 * S + y0) * S + z0);
    float2 A = __ldg(p);
    float2 B = __ldg(p + SS);
    HF u;
    u.f = A.x; float2 al = __half22float2(u.h);
    u.f = A.y; float2 ah = __half22float2(u.h);
    u.f = B.x; float2 bl = __half22float2(u.h);
    u.f = B.y; float2 bh = __half22float2(u.h);
    float a0 = fmaf(fz, al.y - al.x, al.x);
    float a1 = fmaf(fz, ah.y - ah.x, ah.x);
    float b0 = fmaf(fz, bl.y - bl.x, bl.x);
    float b1 = fmaf(fz, bh.y - bh.x, bh.x);
    float va = fmaf(fy, a1 - a0, a0);
    float vb = fmaf(fy, b1 - b0, b0);
    return fmaf(fx, vb - va, va);
}

// shared ray setup
__device__ __forceinline__ void ray_setup(const float* __restrict__ poses,
                                          int v, int w, int h,
                                          float& ox, float& oy, float& oz,
                                          float& dx, float& dy, float& dz) {
    const float offx[3] = {0.0f, 36.0f, 40.0f};
    const float offz[3] = {0.0f, 44.0f, 23.0f};
    const float* M = poses + v * 16;
    ox = M[3]  / 0.0301f + offx[v];
    oy = M[7]  / 0.0301f;
    oz = M[11] / 0.0301f + offz[v];
    float uu = ((float)w - 160.0f) / 277.0f;
    float vv = ((float)h - 120.0f) / 277.0f;
    dx = M[0] * uu + M[1] * vv + M[2];
    dy = M[4] * uu + M[5] * vv + M[6];
    dz = M[8] * uu + M[9] * vv + M[10];
    float nrm = sqrtf(dx * dx + dy * dy + dz * dz);
    dx /= nrm; dy /= nrm; dz /= nrm;
}

// ---------------------------------------------------------------------------
// Kernel 2: ray march only -> write t. 7 blocks/SM => entire grid is ONE wave.
// grid (10, 30, 3), block 256, 8x4 warp tiles
// ---------------------------------------------------------------------------
__global__ __launch_bounds__(256, 7) void march_kernel(
        const float* __restrict__ poses) {
    int tid = threadIdx.x;
    int warp = tid >> 5, lane = tid & 31;
    int wx = warp & 3, wy = warp >> 2;
    int lx = lane & 7, ly = lane >> 3;
    int w = blockIdx.x * 32 + wx * 8 + lx;
    int h = blockIdx.y * 8 + wy * 4 + ly;
    int v = blockIdx.z;

    float ox, oy, oz, dx, dy, dz;
    ray_setup(poses, v, w, h, ox, oy, oz, dx, dy, dz);

    float t = 0.0f;
    bool alive = true;
#pragma unroll 1
    for (int it = 0; it < NSTEP; ++it) {
        if (alive) {
            float px = fmaf(t, dx, ox);
            float py = fmaf(t, dy, oy);
            float pz = fmaf(t, dz, oz);
            bool dead = (px < 0.0f && dx <= 0.0f) || (px > 159.0f && dx >= 0.0f)
                     || (py < 0.0f && dy <= 0.0f) || (py > 159.0f && dy >= 0.0f)
                     || (pz < 0.0f && dz <= 0.0f) || (pz > 159.0f && dz >= 0.0f);
            if (dead) {
                alive = false;
            } else {
                float cx = fminf(fmaxf(px, 0.0f), CLAMP_HI);
                float cy = fminf(fmaxf(py, 0.0f), CLAMP_HI);
                float cz = fminf(fmaxf(pz, 0.0f), CLAMP_HI);
                int x0 = (int)cx, y0 = (int)cy, z0 = (int)cz;
                float s = sdf_sample_h(x0, y0, z0,
                                       cx - (float)x0, cy - (float)y0, cz - (float)z0);
                t = fmaf(fmaxf(s, 0.25f), 2.0f, t);
            }
        }
        if (__all_sync(0xffffffffu, !alive)) break;
    }

    g_tbuf[(v * IMG_H + h) * IMG_W + w] = t;
}

// 3-level separable weights for resized-trilerp-of-source-trilerp along one axis
__device__ __forceinline__ void axis_w(int c0, float f, float* W, int* g) {
    float cc0 = (c0 * 95.0f) / 159.0f;
    int b0 = (int)cc0; float f0 = cc0 - (float)b0;
    float cc1 = ((c0 + 1) * 95.0f) / 159.0f;
    int b1 = (int)cc1; float f1 = cc1 - (float)b1;
    int l = b1 - b0;                    // 0 or 1
    float g0 = 1.0f - f;
    float wa = f * (1.0f - f1), wb = f * f1;
    W[0] = g0 * (1.0f - f0) + (l == 0 ? wa : 0.0f);
    W[1] = g0 * f0 + (l == 0 ? wb : wa);
    W[2] = (l == 0 ? 0.0f : wb);
    g[0] = b0;
    g[1] = min(b0 + 1, DG - 1);
    g[2] = min(b0 + 2, DG - 1);
}

__device__ __forceinline__ float gather27(const float* __restrict__ src,
                                          const int* gx, const int* gy, const int* gz,
                                          const float* Wx, const float* Wy, const float* Wz) {
    float acc = 0.0f;
#pragma unroll
    for (int ia = 0; ia < 3; ia++) {
        float accy = 0.0f;
#pragma unroll
        for (int ib = 0; ib < 3; ib++) {
            const float* rr = src + (gx[ia] * DG + gy[ib]) * DG;
            float accz = __ldg(rr + gz[0]) * Wz[0]
                       + __ldg(rr + gz[1]) * Wz[1]
                       + __ldg(rr + gz[2]) * Wz[2];
            accy = fmaf(Wy[ib], accz, accy);
        }
        acc = fmaf(Wx[ia], accy, acc);
    }
    return acc;
}

// ---------------------------------------------------------------------------
// Kernel 3: shade + loss. One thread per pixel; fused deterministic reduce.
// ---------------------------------------------------------------------------
__global__ __launch_bounds__(256) void shade_kernel(
        const float* __restrict__ rgb,
        const float* __restrict__ sem,
        const float* __restrict__ poses,
        const float* __restrict__ views,
        float* __restrict__ out) {
    int tid = threadIdx.x;
    int pix = blockIdx.x * 256 + tid;
    int v = pix / (IMG_H * IMG_W);
    int r = pix % (IMG_H * IMG_W);
    int h = r / IMG_W;
    int w = r % IMG_W;

    float ox, oy, oz, dx, dy, dz;
    ray_setup(poses, v, w, h, ox, oy, oz, dx, dy, dz);

    float t = g_tbuf[pix];
    float px = fmaf(t, dx, ox);
    float py = fmaf(t, dy, oy);
    float pz = fmaf(t, dz, oz);

    float cx = fminf(fmaxf(px, 0.0f), CLAMP_HI);
    float cy = fminf(fmaxf(py, 0.0f), CLAMP_HI);
    float cz = fminf(fmaxf(pz, 0.0f), CLAMP_HI);
    int x0 = (int)cx, y0 = (int)cy, z0 = (int)cz;
    float fx = cx - (float)x0, fy = cy - (float)y0, fz = cz - (float)z0;

    float s = sdf_sample_h(x0, y0, z0, fx, fy, fz);

    bool inside = (px >= 0.0f) && (px <= 159.0f)
               && (py >= 0.0f) && (py <= 159.0f)
               && (pz >= 0.0f) && (pz <= 159.0f);
    bool valid = inside && (fabsf(s) < 1.0f);

    float contrib = 0.0f;
    int cnt = 0;
    if (valid) {
        float Wx[3], Wy[3], Wz[3];
        int gx[3], gy[3], gz[3];
        axis_w(x0, fx, Wx, gx);
        axis_w(y0, fy, Wy, gy);
        axis_w(z0, fz, Wz, gz);

        float c0 = gather27(rgb,           gx, gy, gz, Wx, Wy, Wz);
        float c1 = gather27(rgb + DG3,     gx, gy, gz, Wx, Wy, Wz);
        float c2 = gather27(rgb + 2 * DG3, gx, gy, gz, Wx, Wy, Wz);

        int nx0 = min((int)(x0 * 0.6f), DG - 1);
        int nx1 = min((int)((x0 + 1) * 0.6f), DG - 1);
        int ny0 = min((int)(y0 * 0.6f), DG - 1);
        int ny1 = min((int)((y0 + 1) * 0.6f), DG - 1);
        int nz0 = min((int)(z0 * 0.6f), DG - 1);
        int nz1 = min((int)((z0 + 1) * 0.6f), DG - 1);
        float gxf = 1.0f - fx, gyf = 1.0f - fy, gzf = 1.0f - fz;
        const float* s00 = sem + (nx0 * DG + ny0) * DG;
        const float* s01 = sem + (nx0 * DG + ny1) * DG;
        const float* s10 = sem + (nx1 * DG + ny0) * DG;
        const float* s11 = sem + (nx1 * DG + ny1) * DG;
        float wv = gxf * gyf * (gzf * __ldg(s00 + nz0) + fz * __ldg(s00 + nz1))
                 + gxf * fy  * (gzf * __ldg(s01 + nz0) + fz * __ldg(s01 + nz1))
                 + fx  * gyf * (gzf * __ldg(s10 + nz0) + fz * __ldg(s10 + nz1))
                 + fx  * fy  * (gzf * __ldg(s11 + nz0) + fz * __ldg(s11 + nz1));

        const float* vw = views + (size_t)pix * 3;
        contrib = (fabsf(c0 - vw[0]) + fabsf(c1 - vw[1]) + fabsf(c2 - vw[2])) * wv;
        cnt = 1;
    }

    __shared__ float ssum[256];
    __shared__ int scnt[256];
    ssum[tid] = contrib;
    scnt[tid] = cnt;
    __syncthreads();
#pragma unroll
    for (int o = 128; o > 0; o >>= 1) {
        if (tid < o) {
            ssum[tid] += ssum[tid + o];
            scnt[tid] += scnt[tid + o];
        }
        __syncthreads();
    }
    __shared__ bool amLast;
    if (tid == 0) {
        g_psum[blockIdx.x] = ssum[0];
        g_pcnt[blockIdx.x] = scnt[0];
        __threadfence();
        int tk = atomicAdd(&g_count, 1);
        amLast = (tk == NBLK - 1);
    }
    __syncthreads();

    if (amLast) {
        float sacc = 0.0f; int cacc = 0;
        for (int k = tid; k < NBLK; k += 256) {
            sacc += g_psum[k];
            cacc += g_pcnt[k];
        }
        ssum[tid] = sacc;
        scnt[tid] = cacc;
        __syncthreads();
#pragma unroll
        for (int o = 128; o > 0; o >>= 1) {
            if (tid < o) {
                ssum[tid] += ssum[tid + o];
                scnt[tid] += scnt[tid + o];
            }
            __syncthreads();
        }
        if (tid == 0) {
            float nv = 3.0f * (float)scnt[0];
            out[0] = 8.0f * ssum[0] / fmaxf(nv, 1.0f);
            g_count = 0;
        }
    }
}

// ---------------------------------------------------------------------------
extern "C" void kernel_launch(void* const* d_in, const int* in_sizes, int n_in,
                              void* d_out, int out_size) {
    const float* sdf   = (const float*)d_in[0];
    const float* rgb   = (const float*)d_in[1];
    const float* sem   = (const float*)d_in[2];
    const float* poses = (const float*)d_in[3];
    const float* views = (const float*)d_in[4];

    resize_sdf_kernel<<<S * S, 192>>>(sdf);
    dim3 mg(IMG_W / 32, IMG_H / 8, NVIEW);
    march_kernel<<<mg, 256>>>(poses);
    shade_kernel<<<NBLK, 256>>>(rgb, sem, poses, views, (float*)d_out);
}

// round 13
// speedup vs baseline: 1.3110x; 1.1135x over previous
#include <cuda_runtime.h>
#include <cuda_fp16.h>

#define S 160
#define SS (S*S)
#define S3 (S*S*S)
#define DG 96
#define DG2 (DG*DG)
#define DG3 (DG*DG*DG)
#define IMG_H 240
#define IMG_W 320
#define NVIEW 3
#define NSTEP 64
#define CLAMP_HI 158.999f          // f32(160 - 1.001)
#define NBLK 900
#define JPB 8                       // j-rows per resize block

// packed resized SDF, half precision:
//   g_sdfh[(x*S+y)*S+z] = float2 whose bits are two __half2:
//     .x bits = (S[y][z], S[y][z+1])   .y bits = (S[y+1][z], S[y+1][z+1])
__device__ float2 g_sdfh[S3];      // 32 MB
__device__ float  g_psum[NBLK];
__device__ int    g_pcnt[NBLK];
__device__ int    g_count;         // zero-initialized; reset after use

union HF { __half2 h; float f; };

// ---------------------------------------------------------------------------
// Kernel 1: fat-block separable SDF resize 96^3 -> 160^3 (minus TRUNC).
// grid (S, S/JPB), block 256. Stage 1: xy-bilerp rows j0..j0+JPB into smem.
// Stage 2: z-lerp + pack half4, 8*160 outputs per block, coalesced stores.
// ---------------------------------------------------------------------------
__global__ __launch_bounds__(256) void resize_sdf_kernel(const float* __restrict__ sdf) {
    int i  = blockIdx.x;           // 0..159
    int j0 = blockIdx.y * JPB;     // 0,8,...,152
    int t  = threadIdx.x;          // 256

    float cx = (i * 95.0f) / 159.0f;
    int x0 = (int)cx; float fx = cx - (float)x0; int x1 = min(x0 + 1, DG - 1);
    int xs = (x1 - x0) * DG2;
    float gxf = 1.0f - fx;

    __shared__ float ls[JPB + 1][DG];   // rows j0..j0+JPB (clamped)

    for (int q = t; q < (JPB + 1) * DG; q += 256) {
        int jl = q / DG, z = q - jl * DG;
        int jj = min(j0 + jl, S - 1);
        float cy = (jj * 95.0f) / 159.0f;
        int y0 = (int)cy; float fy = cy - (float)y0; int y1 = min(y0 + 1, DG - 1);
        int base = (x0 * DG + y0) * DG + z;
        int ys = (y1 - y0) * DG;
        float gyf = 1.0f - fy;
        ls[jl][z] = __ldg(sdf + base) * (gxf * gyf) + __ldg(sdf + base + ys) * (gxf * fy)
                  + __ldg(sdf + base + xs) * (fx * gyf) + __ldg(sdf + base + xs + ys) * (fx * fy);
    }
    __syncthreads();

    for (int o = t; o < JPB * S; o += 256) {
        int jl = o / S, z = o - jl * S;

        float czf = (z * 95.0f) / 159.0f;
        int z0 = (int)czf; float fz = czf - (float)z0; int z1 = min(z0 + 1, DG - 1);
        int zb = min(z + 1, S - 1);
        float czg = (zb * 95.0f) / 159.0f;
        int w0 = (int)czg; float fw = czg - (float)w0; int w1 = min(w0 + 1, DG - 1);

        const float* A = ls[jl];
        const float* B = ls[jl + 1];
        float vA0 = fmaf(fz, A[z1] - A[z0], A[z0]) - 1.5f;
        float vA1 = fmaf(fw, A[w1] - A[w0], A[w0]) - 1.5f;
        float vB0 = fmaf(fz, B[z1] - B[z0], B[z0]) - 1.5f;
        float vB1 = fmaf(fw, B[w1] - B[w0], B[w0]) - 1.5f;

        HF lo, hi;
        lo.h = __floats2half2_rn(vA0, vA1);
        hi.h = __floats2half2_rn(vB0, vB1);
        g_sdfh[(i * S + (j0 + jl)) * S + z] = make_float2(lo.f, hi.f);
    }
}

// ---------------------------------------------------------------------------
// half4 SDF sample: 2x 8B loads, fp32 lerp
// ---------------------------------------------------------------------------
__device__ __forceinline__ float sdf_sample_h(int x0, int y0, int z0,
                                              float fx, float fy, float fz) {
    const float2* p = g_sdfh + ((x0 * S + y0) * S + z0);
    float2 A = __ldg(p);
    float2 B = __ldg(p + SS);
    HF u;
    u.f = A.x; float2 al = __half22float2(u.h);
    u.f = A.y; float2 ah = __half22float2(u.h);
    u.f = B.x; float2 bl = __half22float2(u.h);
    u.f = B.y; float2 bh = __half22float2(u.h);
    float a0 = fmaf(fz, al.y - al.x, al.x);
    float a1 = fmaf(fz, ah.y - ah.x, ah.x);
    float b0 = fmaf(fz, bl.y - bl.x, bl.x);
    float b1 = fmaf(fz, bh.y - bh.x, bh.x);
    float va = fmaf(fy, a1 - a0, a0);
    float vb = fmaf(fy, b1 - b0, b0);
    return fmaf(fx, vb - va, va);
}

// 3-level separable weights for resized-trilerp-of-source-trilerp along one axis
__device__ __forceinline__ void axis_w(int c0, float f, float* W, int* g) {
    float cc0 = (c0 * 95.0f) / 159.0f;
    int b0 = (int)cc0; float f0 = cc0 - (float)b0;
    float cc1 = ((c0 + 1) * 95.0f) / 159.0f;
    int b1 = (int)cc1; float f1 = cc1 - (float)b1;
    int l = b1 - b0;                    // 0 or 1
    float g0 = 1.0f - f;
    float wa = f * (1.0f - f1), wb = f * f1;
    W[0] = g0 * (1.0f - f0) + (l == 0 ? wa : 0.0f);
    W[1] = g0 * f0 + (l == 0 ? wb : wa);
    W[2] = (l == 0 ? 0.0f : wb);
    g[0] = b0;
    g[1] = min(b0 + 1, DG - 1);
    g[2] = min(b0 + 2, DG - 1);
}

__device__ __forceinline__ float gather27(const float* __restrict__ src,
                                          const int* gx, const int* gy, const int* gz,
                                          const float* Wx, const float* Wy, const float* Wz) {
    float acc = 0.0f;
#pragma unroll
    for (int ia = 0; ia < 3; ia++) {
        float accy = 0.0f;
#pragma unroll
        for (int ib = 0; ib < 3; ib++) {
            const float* rr = src + (gx[ia] * DG + gy[ib]) * DG;
            float accz = __ldg(rr + gz[0]) * Wz[0]
                       + __ldg(rr + gz[1]) * Wz[1]
                       + __ldg(rr + gz[2]) * Wz[2];
            accy = fmaf(Wy[ib], accz, accy);
        }
        acc = fmaf(Wx[ia], accy, acc);
    }
    return acc;
}

// ---------------------------------------------------------------------------
// Kernel 2: fused march + shade + loss. grid (10, 30, 3), block 256.
// ---------------------------------------------------------------------------
__global__ __launch_bounds__(256) void march_kernel(
        const float* __restrict__ rgb,
        const float* __restrict__ sem,
        const float* __restrict__ poses,
        const float* __restrict__ views,
        float* __restrict__ out) {
    int tid = threadIdx.x;
    int warp = tid >> 5, lane = tid & 31;
    int wx = warp & 3, wy = warp >> 2;
    int lx = lane & 7, ly = lane >> 3;
    int w = blockIdx.x * 32 + wx * 8 + lx;
    int h = blockIdx.y * 8 + wy * 4 + ly;
    int v = blockIdx.z;

    const float offx[3] = {0.0f, 36.0f, 40.0f};
    const float offz[3] = {0.0f, 44.0f, 23.0f};
    const float* M = poses + v * 16;
    float ox = M[3]  / 0.0301f + offx[v];
    float oy = M[7]  / 0.0301f;
    float oz = M[11] / 0.0301f + offz[v];
    float uu = ((float)w - 160.0f) / 277.0f;
    float vv = ((float)h - 120.0f) / 277.0f;
    float dx = M[0] * uu + M[1] * vv + M[2];
    float dy = M[4] * uu + M[5] * vv + M[6];
    float dz = M[8] * uu + M[9] * vv + M[10];
    float nrm = sqrtf(dx * dx + dy * dy + dz * dz);
    dx /= nrm; dy /= nrm; dz /= nrm;

    float t = 0.0f;
    bool alive = true;
#pragma unroll 1
    for (int it = 0; it < NSTEP; ++it) {
        if (alive) {
            float px = fmaf(t, dx, ox);
            float py = fmaf(t, dy, oy);
            float pz = fmaf(t, dz, oz);
            bool dead = (px < 0.0f && dx <= 0.0f) || (px > 159.0f && dx >= 0.0f)
                     || (py < 0.0f && dy <= 0.0f) || (py > 159.0f && dy >= 0.0f)
                     || (pz < 0.0f && dz <= 0.0f) || (pz > 159.0f && dz >= 0.0f);
            if (dead) {
                alive = false;
            } else {
                float cx = fminf(fmaxf(px, 0.0f), CLAMP_HI);
                float cy = fminf(fmaxf(py, 0.0f), CLAMP_HI);
                float cz = fminf(fmaxf(pz, 0.0f), CLAMP_HI);
                int x0 = (int)cx, y0 = (int)cy, z0 = (int)cz;
                float s = sdf_sample_h(x0, y0, z0,
                                       cx - (float)x0, cy - (float)y0, cz - (float)z0);
                t = fmaf(fmaxf(s, 0.25f), 2.0f, t);
            }
        }
        if (__all_sync(0xffffffffu, !alive)) break;
    }

    float contrib = 0.0f;
    int cnt = 0;
    if (alive) {
        float px = fmaf(t, dx, ox);
        float py = fmaf(t, dy, oy);
        float pz = fmaf(t, dz, oz);
        float cx = fminf(fmaxf(px, 0.0f), CLAMP_HI);
        float cy = fminf(fmaxf(py, 0.0f), CLAMP_HI);
        float cz = fminf(fmaxf(pz, 0.0f), CLAMP_HI);
        int x0 = (int)cx, y0 = (int)cy, z0 = (int)cz;
        float fx = cx - (float)x0, fy = cy - (float)y0, fz = cz - (float)z0;

        float s = sdf_sample_h(x0, y0, z0, fx, fy, fz);

        bool inside = (px >= 0.0f) && (px <= 159.0f)
                   && (py >= 0.0f) && (py <= 159.0f)
                   && (pz >= 0.0f) && (pz <= 159.0f);
        bool valid = inside && (fabsf(s) < 1.0f);

        if (valid) {
            float Wx[3], Wy[3], Wz[3];
            int gx[3], gy[3], gz[3];
            axis_w(x0, fx, Wx, gx);
            axis_w(y0, fy, Wy, gy);
            axis_w(z0, fz, Wz, gz);

            float c0 = gather27(rgb,           gx, gy, gz, Wx, Wy, Wz);
            float c1 = gather27(rgb + DG3,     gx, gy, gz, Wx, Wy, Wz);
            float c2 = gather27(rgb + 2 * DG3, gx, gy, gz, Wx, Wy, Wz);

            int nx0 = min((int)(x0 * 0.6f), DG - 1);
            int nx1 = min((int)((x0 + 1) * 0.6f), DG - 1);
            int ny0 = min((int)(y0 * 0.6f), DG - 1);
            int ny1 = min((int)((y0 + 1) * 0.6f), DG - 1);
            int nz0 = min((int)(z0 * 0.6f), DG - 1);
            int nz1 = min((int)((z0 + 1) * 0.6f), DG - 1);
            float gxf = 1.0f - fx, gyf = 1.0f - fy, gzf = 1.0f - fz;
            const float* s00 = sem + (nx0 * DG + ny0) * DG;
            const float* s01 = sem + (nx0 * DG + ny1) * DG;
            const float* s10 = sem + (nx1 * DG + ny0) * DG;
            const float* s11 = sem + (nx1 * DG + ny1) * DG;
            float wv = gxf * gyf * (gzf * __ldg(s00 + nz0) + fz * __ldg(s00 + nz1))
                     + gxf * fy  * (gzf * __ldg(s01 + nz0) + fz * __ldg(s01 + nz1))
                     + fx  * gyf * (gzf * __ldg(s10 + nz0) + fz * __ldg(s10 + nz1))
                     + fx  * fy  * (gzf * __ldg(s11 + nz0) + fz * __ldg(s11 + nz1));

            const float* vw = views + ((size_t)(v * IMG_H + h) * IMG_W + w) * 3;
            contrib = (fabsf(c0 - vw[0]) + fabsf(c1 - vw[1]) + fabsf(c2 - vw[2])) * wv;
            cnt = 1;
        }
    }

    // deterministic block reduction + last-block finish
    __shared__ float ssum[256];
    __shared__ int scnt[256];
    ssum[tid] = contrib;
    scnt[tid] = cnt;
    __syncthreads();
#pragma unroll
    for (int o = 128; o > 0; o >>= 1) {
        if (tid < o) {
            ssum[tid] += ssum[tid + o];
            scnt[tid] += scnt[tid + o];
        }
        __syncthreads();
    }
    int bid = (blockIdx.z * gridDim.y + blockIdx.y) * gridDim.x + blockIdx.x;
    __shared__ bool amLast;
    if (tid == 0) {
        g_psum[bid] = ssum[0];
        g_pcnt[bid] = scnt[0];
        __threadfence();
        int tk = atomicAdd(&g_count, 1);
        amLast = (tk == NBLK - 1);
    }
    __syncthreads();

    if (amLast) {
        float sacc = 0.0f; int cacc = 0;
        for (int k = tid; k < NBLK; k += 256) {
            sacc += g_psum[k];
            cacc += g_pcnt[k];
        }
        ssum[tid] = sacc;
        scnt[tid] = cacc;
        __syncthreads();
#pragma unroll
        for (int o = 128; o > 0; o >>= 1) {
            if (tid < o) {
                ssum[tid] += ssum[tid + o];
                scnt[tid] += scnt[tid + o];
            }
            __syncthreads();
        }
        if (tid == 0) {
            float nv = 3.0f * (float)scnt[0];
            out[0] = 8.0f * ssum[0] / fmaxf(nv, 1.0f);
            g_count = 0;
        }
    }
}

// ---------------------------------------------------------------------------
extern "C" void kernel_launch(void* const* d_in, const int* in_sizes, int n_in,
                              void* d_out, int out_size) {
    const float* sdf   = (const float*)d_in[0];
    const float* rgb   = (const float*)d_in[1];
    const float* sem   = (const float*)d_in[2];
    const float* poses = (const float*)d_in[3];
    const float* views = (const float*)d_in[4];

    dim3 rg(S, S / JPB);
    resize_sdf_kernel<<<rg, 256>>>(sdf);
    dim3 mg(IMG_W / 32, IMG_H / 8, NVIEW);
    march_kernel<<<mg, 256>>>(rgb, sem, poses, views, (float*)d_out);
}

// round 14
// speedup vs baseline: 1.4669x; 1.1189x over previous
#include <cuda_runtime.h>
#include <cuda_fp16.h>

#define S 160
#define SS (S*S)
#define S3 (S*S*S)
#define DG 96
#define DG2 (DG*DG)
#define DG3 (DG*DG*DG)
#define IMG_H 240
#define IMG_W 320
#define NVIEW 3
#define NPIX (NVIEW*IMG_H*IMG_W)   // 230400
#define NSTEP 64
#define CLAMP_HI 158.999f          // f32(160 - 1.001)
#define NBLK 900
#define JPB 8                      // j-rows per resize block

// packed resized SDF, half precision:
//   g_sdfh[(x*S+y)*S+z] = float2 whose bits are two __half2:
//     .x bits = (S[y][z], S[y][z+1])   .y bits = (S[y+1][z], S[y+1][z+1])
__device__ float2 g_sdfh[S3];      // 32 MB
__device__ float  g_tbuf[NPIX];    // final ray parameter t
__device__ float  g_psum[NBLK];
__device__ int    g_pcnt[NBLK];
__device__ int    g_count;         // zero-initialized; reset after use

union HF { __half2 h; float f; };

// ---------------------------------------------------------------------------
// Kernel 1: fat-block separable SDF resize 96^3 -> 160^3 (minus TRUNC).
// grid (S, S/JPB), block 256. (R13, measured ~12us)
// ---------------------------------------------------------------------------
__global__ __launch_bounds__(256) void resize_sdf_kernel(const float* __restrict__ sdf) {
    int i  = blockIdx.x;           // 0..159
    int j0 = blockIdx.y * JPB;     // 0,8,...,152
    int t  = threadIdx.x;          // 256

    float cx = (i * 95.0f) / 159.0f;
    int x0 = (int)cx; float fx = cx - (float)x0; int x1 = min(x0 + 1, DG - 1);
    int xs = (x1 - x0) * DG2;
    float gxf = 1.0f - fx;

    __shared__ float ls[JPB + 1][DG];   // rows j0..j0+JPB (clamped)

    for (int q = t; q < (JPB + 1) * DG; q += 256) {
        int jl = q / DG, z = q - jl * DG;
        int jj = min(j0 + jl, S - 1);
        float cy = (jj * 95.0f) / 159.0f;
        int y0 = (int)cy; float fy = cy - (float)y0; int y1 = min(y0 + 1, DG - 1);
        int base = (x0 * DG + y0) * DG + z;
        int ys = (y1 - y0) * DG;
        float gyf = 1.0f - fy;
        ls[jl][z] = __ldg(sdf + base) * (gxf * gyf) + __ldg(sdf + base + ys) * (gxf * fy)
                  + __ldg(sdf + base + xs) * (fx * gyf) + __ldg(sdf + base + xs + ys) * (fx * fy);
    }
    __syncthreads();

    for (int o = t; o < JPB * S; o += 256) {
        int jl = o / S, z = o - jl * S;

        float czf = (z * 95.0f) / 159.0f;
        int z0 = (int)czf; float fz = czf - (float)z0; int z1 = min(z0 + 1, DG - 1);
        int zb = min(z + 1, S - 1);
        float czg = (zb * 95.0f) / 159.0f;
        int w0 = (int)czg; float fw = czg - (float)w0; int w1 = min(w0 + 1, DG - 1);

        const float* A = ls[jl];
        const float* B = ls[jl + 1];
        float vA0 = fmaf(fz, A[z1] - A[z0], A[z0]) - 1.5f;
        float vA1 = fmaf(fw, A[w1] - A[w0], A[w0]) - 1.5f;
        float vB0 = fmaf(fz, B[z1] - B[z0], B[z0]) - 1.5f;
        float vB1 = fmaf(fw, B[w1] - B[w0], B[w0]) - 1.5f;

        HF lo, hi;
        lo.h = __floats2half2_rn(vA0, vA1);
        hi.h = __floats2half2_rn(vB0, vB1);
        g_sdfh[(i * S + (j0 + jl)) * S + z] = make_float2(lo.f, hi.f);
    }
}

// ---------------------------------------------------------------------------
// half4 SDF sample: 2x 8B loads, fp32 lerp
// ---------------------------------------------------------------------------
__device__ __forceinline__ float sdf_sample_h(int x0, int y0, int z0,
                                              float fx, float fy, float fz) {
    const float2* p = g_sdfh + ((x0 * S + y0) * S + z0);
    float2 A = __ldg(p);
    float2 B = __ldg(p + SS);
    HF u;
    u.f = A.x; float2 al = __half22float2(u.h);
    u.f = A.y; float2 ah = __half22float2(u.h);
    u.f = B.x; float2 bl = __half22float2(u.h);
    u.f = B.y; float2 bh = __half22float2(u.h);
    float a0 = fmaf(fz, al.y - al.x, al.x);
    float a1 = fmaf(fz, ah.y - ah.x, ah.x);
    float b0 = fmaf(fz, bl.y - bl.x, bl.x);
    float b1 = fmaf(fz, bh.y - bh.x, bh.x);
    float va = fmaf(fy, a1 - a0, a0);
    float vb = fmaf(fy, b1 - b0, b0);
    return fmaf(fx, vb - va, va);
}

// shared ray setup
__device__ __forceinline__ void ray_setup(const float* __restrict__ poses,
                                          int v, int w, int h,
                                          float& ox, float& oy, float& oz,
                                          float& dx, float& dy, float& dz) {
    const float offx[3] = {0.0f, 36.0f, 40.0f};
    const float offz[3] = {0.0f, 44.0f, 23.0f};
    const float* M = poses + v * 16;
    ox = M[3]  / 0.0301f + offx[v];
    oy = M[7]  / 0.0301f;
    oz = M[11] / 0.0301f + offz[v];
    float uu = ((float)w - 160.0f) / 277.0f;
    float vv = ((float)h - 120.0f) / 277.0f;
    dx = M[0] * uu + M[1] * vv + M[2];
    dy = M[4] * uu + M[5] * vv + M[6];
    dz = M[8] * uu + M[9] * vv + M[10];
    float nrm = sqrtf(dx * dx + dy * dy + dz * dz);
    dx /= nrm; dy /= nrm; dz /= nrm;
}

// exit time through the far plane along one axis (box convex: beyond this the
// ray is outside-and-receding on that axis => permanently invalid)
__device__ __forceinline__ float axis_exit(float o, float d) {
    if (d > 0.0f) return (159.0f - o) / d;
    if (d < 0.0f) return -o / d;
    return (o >= 0.0f && o <= 159.0f) ? 3.0e38f : -1.0f;
}

// ---------------------------------------------------------------------------
// Kernel 2: branch-free ray march -> write t. Single wave (7 blocks/SM).
// grid (10, 30, 3), block 256, 8x4 warp tiles
// ---------------------------------------------------------------------------
__global__ __launch_bounds__(256, 7) void march_kernel(
        const float* __restrict__ poses) {
    int tid = threadIdx.x;
    int warp = tid >> 5, lane = tid & 31;
    int wx = warp & 3, wy = warp >> 2;
    int lx = lane & 7, ly = lane >> 3;
    int w = blockIdx.x * 32 + wx * 8 + lx;
    int h = blockIdx.y * 8 + wy * 4 + ly;
    int v = blockIdx.z;

    float ox, oy, oz, dx, dy, dz;
    ray_setup(poses, v, w, h, ox, oy, oz, dx, dy, dz);

    float t_exit = fminf(fminf(axis_exit(ox, dx), axis_exit(oy, dy)),
                         axis_exit(oz, dz));

    float t = 0.0f;
#pragma unroll 1
    for (int it = 0; it < NSTEP; ++it) {
        float cx = fminf(fmaxf(fmaf(t, dx, ox), 0.0f), CLAMP_HI);
        float cy = fminf(fmaxf(fmaf(t, dy, oy), 0.0f), CLAMP_HI);
        float cz = fminf(fmaxf(fmaf(t, dz, oz), 0.0f), CLAMP_HI);
        int x0 = (int)cx, y0 = (int)cy, z0 = (int)cz;
        float s = sdf_sample_h(x0, y0, z0,
                               cx - (float)x0, cy - (float)y0, cz - (float)z0);
        t = fmaf(fmaxf(s, 0.25f), 2.0f, t);
        if (__all_sync(0xffffffffu, t > t_exit)) break;
    }

    g_tbuf[(v * IMG_H + h) * IMG_W + w] = t;
}

// 3-level separable weights for resized-trilerp-of-source-trilerp along one axis
__device__ __forceinline__ void axis_w(int c0, float f, float* W, int* g) {
    float cc0 = (c0 * 95.0f) / 159.0f;
    int b0 = (int)cc0; float f0 = cc0 - (float)b0;
    float cc1 = ((c0 + 1) * 95.0f) / 159.0f;
    int b1 = (int)cc1; float f1 = cc1 - (float)b1;
    int l = b1 - b0;                    // 0 or 1
    float g0 = 1.0f - f;
    float wa = f * (1.0f - f1), wb = f * f1;
    W[0] = g0 * (1.0f - f0) + (l == 0 ? wa : 0.0f);
    W[1] = g0 * f0 + (l == 0 ? wb : wa);
    W[2] = (l == 0 ? 0.0f : wb);
    g[0] = b0;
    g[1] = min(b0 + 1, DG - 1);
    g[2] = min(b0 + 2, DG - 1);
}

__device__ __forceinline__ float gather27(const float* __restrict__ src,
                                          const int* gx, const int* gy, const int* gz,
                                          const float* Wx, const float* Wy, const float* Wz) {
    float acc = 0.0f;
#pragma unroll
    for (int ia = 0; ia < 3; ia++) {
        float accy = 0.0f;
#pragma unroll
        for (int ib = 0; ib < 3; ib++) {
            const float* rr = src + (gx[ia] * DG + gy[ib]) * DG;
            float accz = __ldg(rr + gz[0]) * Wz[0]
                       + __ldg(rr + gz[1]) * Wz[1]
                       + __ldg(rr + gz[2]) * Wz[2];
            accy = fmaf(Wy[ib], accz, accy);
        }
        acc = fmaf(Wx[ia], accy, acc);
    }
    return acc;
}

// ---------------------------------------------------------------------------
// Kernel 3: shade + loss. One thread per pixel; fused deterministic reduce.
// ---------------------------------------------------------------------------
__global__ __launch_bounds__(256) void shade_kernel(
        const float* __restrict__ rgb,
        const float* __restrict__ sem,
        const float* __restrict__ poses,
        const float* __restrict__ views,
        float* __restrict__ out) {
    int tid = threadIdx.x;
    int pix = blockIdx.x * 256 + tid;
    int v = pix / (IMG_H * IMG_W);
    int r = pix % (IMG_H * IMG_W);
    int h = r / IMG_W;
    int w = r % IMG_W;

    float ox, oy, oz, dx, dy, dz;
    ray_setup(poses, v, w, h, ox, oy, oz, dx, dy, dz);

    float t = g_tbuf[pix];
    float px = fmaf(t, dx, ox);
    float py = fmaf(t, dy, oy);
    float pz = fmaf(t, dz, oz);

    float cx = fminf(fmaxf(px, 0.0f), CLAMP_HI);
    float cy = fminf(fmaxf(py, 0.0f), CLAMP_HI);
    float cz = fminf(fmaxf(pz, 0.0f), CLAMP_HI);
    int x0 = (int)cx, y0 = (int)cy, z0 = (int)cz;
    float fx = cx - (float)x0, fy = cy - (float)y0, fz = cz - (float)z0;

    float s = sdf_sample_h(x0, y0, z0, fx, fy, fz);

    bool inside = (px >= 0.0f) && (px <= 159.0f)
               && (py >= 0.0f) && (py <= 159.0f)
               && (pz >= 0.0f) && (pz <= 159.0f);
    bool valid = inside && (fabsf(s) < 1.0f);

    float contrib = 0.0f;
    int cnt = 0;
    if (valid) {
        float Wx[3], Wy[3], Wz[3];
        int gx[3], gy[3], gz[3];
        axis_w(x0, fx, Wx, gx);
        axis_w(y0, fy, Wy, gy);
        axis_w(z0, fz, Wz, gz);

        float c0 = gather27(rgb,           gx, gy, gz, Wx, Wy, Wz);
        float c1 = gather27(rgb + DG3,     gx, gy, gz, Wx, Wy, Wz);
        float c2 = gather27(rgb + 2 * DG3, gx, gy, gz, Wx, Wy, Wz);

        int nx0 = min((int)(x0 * 0.6f), DG - 1);
        int nx1 = min((int)((x0 + 1) * 0.6f), DG - 1);
        int ny0 = min((int)(y0 * 0.6f), DG - 1);
        int ny1 = min((int)((y0 + 1) * 0.6f), DG - 1);
        int nz0 = min((int)(z0 * 0.6f), DG - 1);
        int nz1 = min((int)((z0 + 1) * 0.6f), DG - 1);
        float gxf = 1.0f - fx, gyf = 1.0f - fy, gzf = 1.0f - fz;
        const float* s00 = sem + (nx0 * DG + ny0) * DG;
        const float* s01 = sem + (nx0 * DG + ny1) * DG;
        const float* s10 = sem + (nx1 * DG + ny0) * DG;
        const float* s11 = sem + (nx1 * DG + ny1) * DG;
        float wv = gxf * gyf * (gzf * __ldg(s00 + nz0) + fz * __ldg(s00 + nz1))
                 + gxf * fy  * (gzf * __ldg(s01 + nz0) + fz * __ldg(s01 + nz1))
                 + fx  * gyf * (gzf * __ldg(s10 + nz0) + fz * __ldg(s10 + nz1))
                 + fx  * fy  * (gzf * __ldg(s11 + nz0) + fz * __ldg(s11 + nz1));

        const float* vw = views + (size_t)pix * 3;
        contrib = (fabsf(c0 - vw[0]) + fabsf(c1 - vw[1]) + fabsf(c2 - vw[2])) * wv;
        cnt = 1;
    }

    __shared__ float ssum[256];
    __shared__ int scnt[256];
    ssum[tid] = contrib;
    scnt[tid] = cnt;
    __syncthreads();
#pragma unroll
    for (int o = 128; o > 0; o >>= 1) {
        if (tid < o) {
            ssum[tid] += ssum[tid + o];
            scnt[tid] += scnt[tid + o];
        }
        __syncthreads();
    }
    __shared__ bool amLast;
    if (tid == 0) {
        g_psum[blockIdx.x] = ssum[0];
        g_pcnt[blockIdx.x] = scnt[0];
        __threadfence();
        int tk = atomicAdd(&g_count, 1);
        amLast = (tk == NBLK - 1);
    }
    __syncthreads();

    if (amLast) {
        float sacc = 0.0f; int cacc = 0;
        for (int k = tid; k < NBLK; k += 256) {
            sacc += g_psum[k];
            cacc += g_pcnt[k];
        }
        ssum[tid] = sacc;
        scnt[tid] = cacc;
        __syncthreads();
#pragma unroll
        for (int o = 128; o > 0; o >>= 1) {
            if (tid < o) {
                ssum[tid] += ssum[tid + o];
                scnt[tid] += scnt[tid + o];
            }
            __syncthreads();
        }
        if (tid == 0) {
            float nv = 3.0f * (float)scnt[0];
            out[0] = 8.0f * ssum[0] / fmaxf(nv, 1.0f);
            g_count = 0;
        }
    }
}

// ---------------------------------------------------------------------------
extern "C" void kernel_launch(void* const* d_in, const int* in_sizes, int n_in,
                              void* d_out, int out_size) {
    const float* sdf   = (const float*)d_in[0];
    const float* rgb   = (const float*)d_in[1];
    const float* sem   = (const float*)d_in[2];
    const float* poses = (const float*)d_in[3];
    const float* views = (const float*)d_in[4];

    dim3 rg(S, S / JPB);
    resize_sdf_kernel<<<rg, 256>>>(sdf);
    dim3 mg(IMG_W / 32, IMG_H / 8, NVIEW);
    march_kernel<<<mg, 256>>>(poses);
    shade_kernel<<<NBLK, 256>>>(rgb, sem, poses, views, (float*)d_out);
}

// round 15
// speedup vs baseline: 1.5903x; 1.0841x over previous
#include <cuda_runtime.h>
#include <cuda_fp16.h>

#define S 160
#define SS (S*S)
#define S3 (S*S*S)
#define DG 96
#define DG2 (DG*DG)
#define DG3 (DG*DG*DG)
#define IMG_H 240
#define IMG_W 320
#define NVIEW 3
#define NPIX (NVIEW*IMG_H*IMG_W)   // 230400
#define NSTEP 64
#define CLAMP_HI 158.999f          // f32(160 - 1.001)
#define NBLK 900
#define JPB 8                      // j-rows per resize block

// packed resized SDF, half precision:
//   g_sdfh[(x*S+y)*S+z] = float2 whose bits are two __half2:
//     .x bits = (S[y][z], S[y][z+1])   .y bits = (S[y+1][z], S[y+1][z+1])
__device__ float2 g_sdfh[S3];      // 32 MB
__device__ float  g_tbuf[NPIX];    // final ray parameter t
__device__ float  g_psum[NBLK];
__device__ int    g_pcnt[NBLK];
__device__ int    g_count;         // zero-initialized; reset after use

union HF { __half2 h; float f; };

// ---------------------------------------------------------------------------
// Kernel 1: fat-block separable SDF resize with smem coefficient tables.
// grid (S, S/JPB), block 256.
// ---------------------------------------------------------------------------
__global__ __launch_bounds__(256) void resize_sdf_kernel(const float* __restrict__ sdf) {
    int i  = blockIdx.x;           // 0..159
    int j0 = blockIdx.y * JPB;     // 0,8,...,152
    int t  = threadIdx.x;          // 256

    __shared__ float ls[JPB + 1][DG];   // xy-bilerped rows j0..j0+JPB
    __shared__ float zfrac[S];          // fz per output z
    __shared__ int   zidx[S];           // z0 per output z
    __shared__ int   ybase[JPB + 1];    // (x0*DG+y0)*DG per row
    __shared__ int   ystep[JPB + 1];    // (y1-y0)*DG per row
    __shared__ float4 ywt[JPB + 1];     // bilerp weights per row
    __shared__ int   xstep;             // (x1-x0)*DG2

    // stage 0: coefficient tables (all divs happen once here)
    if (t < S) {
        float czf = (t * 95.0f) / 159.0f;   // identical expression as before
        int z0 = (int)czf;
        zidx[t]  = z0;
        zfrac[t] = czf - (float)z0;
    } else if (t < S + JPB + 1) {
        int jl = t - S;
        float cx = (i * 95.0f) / 159.0f;
        int x0 = (int)cx; float fx = cx - (float)x0; int x1 = min(x0 + 1, DG - 1);
        int jj = min(j0 + jl, S - 1);
        float cy = (jj * 95.0f) / 159.0f;
        int y0 = (int)cy; float fy = cy - (float)y0; int y1 = min(y0 + 1, DG - 1);
        float gxf = 1.0f - fx, gyf = 1.0f - fy;
        ybase[jl] = (x0 * DG + y0) * DG;
        ystep[jl] = (y1 - y0) * DG;
        ywt[jl] = make_float4(gxf * gyf, gxf * fy, fx * gyf, fx * fy);
        if (jl == 0) xstep = (x1 - x0) * DG2;
    }
    __syncthreads();

    // stage 1: xy-bilerp rows into smem (4 LDG + 4 FMA each)
    int xs = xstep;
    for (int q = t; q < (JPB + 1) * DG; q += 256) {
        int jl = q / DG, z = q - jl * DG;
        int base = ybase[jl] + z;
        int ys = ystep[jl];
        float4 wv = ywt[jl];
        ls[jl][z] = __ldg(sdf + base) * wv.x + __ldg(sdf + base + ys) * wv.y
                  + __ldg(sdf + base + xs) * wv.z + __ldg(sdf + base + xs + ys) * wv.w;
    }
    __syncthreads();

    // stage 2: z-lerp via tables + pack half4 (identical math as before)
    for (int o = t; o < JPB * S; o += 256) {
        int jl = o / S, z = o - jl * S;

        int z0 = zidx[z];           float fz = zfrac[z];
        int z1 = min(z0 + 1, DG - 1);
        int zb = min(z + 1, S - 1);
        int w0 = zidx[zb];          float fw = zfrac[zb];
        int w1 = min(w0 + 1, DG - 1);

        const float* A = ls[jl];
        const float* B = ls[jl + 1];
        float vA0 = fmaf(fz, A[z1] - A[z0], A[z0]) - 1.5f;
        float vA1 = fmaf(fw, A[w1] - A[w0], A[w0]) - 1.5f;
        float vB0 = fmaf(fz, B[z1] - B[z0], B[z0]) - 1.5f;
        float vB1 = fmaf(fw, B[w1] - B[w0], B[w0]) - 1.5f;

        HF lo, hi;
        lo.h = __floats2half2_rn(vA0, vA1);
        hi.h = __floats2half2_rn(vB0, vB1);
        g_sdfh[(i * S + (j0 + jl)) * S + z] = make_float2(lo.f, hi.f);
    }
}

// ---------------------------------------------------------------------------
// half4 SDF sample: 2x 8B loads, fp32 lerp
// ---------------------------------------------------------------------------
__device__ __forceinline__ float sdf_sample_h(int x0, int y0, int z0,
                                              float fx, float fy, float fz) {
    const float2* p = g_sdfh + ((x0 * S + y0) * S + z0);
    float2 A = __ldg(p);
    float2 B = __ldg(p + SS);
    HF u;
    u.f = A.x; float2 al = __half22float2(u.h);
    u.f = A.y; float2 ah = __half22float2(u.h);
    u.f = B.x; float2 bl = __half22float2(u.h);
    u.f = B.y; float2 bh = __half22float2(u.h);
    float a0 = fmaf(fz, al.y - al.x, al.x);
    float a1 = fmaf(fz, ah.y - ah.x, ah.x);
    float b0 = fmaf(fz, bl.y - bl.x, bl.x);
    float b1 = fmaf(fz, bh.y - bh.x, bh.x);
    float va = fmaf(fy, a1 - a0, a0);
    float vb = fmaf(fy, b1 - b0, b0);
    return fmaf(fx, vb - va, va);
}

// shared ray setup
__device__ __forceinline__ void ray_setup(const float* __restrict__ poses,
                                          int v, int w, int h,
                                          float& ox, float& oy, float& oz,
                                          float& dx, float& dy, float& dz) {
    const float offx[3] = {0.0f, 36.0f, 40.0f};
    const float offz[3] = {0.0f, 44.0f, 23.0f};
    const float* M = poses + v * 16;
    ox = M[3]  / 0.0301f + offx[v];
    oy = M[7]  / 0.0301f;
    oz = M[11] / 0.0301f + offz[v];
    float uu = ((float)w - 160.0f) / 277.0f;
    float vv = ((float)h - 120.0f) / 277.0f;
    dx = M[0] * uu + M[1] * vv + M[2];
    dy = M[4] * uu + M[5] * vv + M[6];
    dz = M[8] * uu + M[9] * vv + M[10];
    float nrm = sqrtf(dx * dx + dy * dy + dz * dz);
    dx /= nrm; dy /= nrm; dz /= nrm;
}

// exit time through the far plane along one axis
__device__ __forceinline__ float axis_exit(float o, float d) {
    if (d > 0.0f) return (159.0f - o) / d;
    if (d < 0.0f) return -o / d;
    return (o >= 0.0f && o <= 159.0f) ? 3.0e38f : -1.0f;
}

// ---------------------------------------------------------------------------
// Kernel 2: branch-free ray march -> write t. Single wave (7 blocks/SM).
// grid (10, 30, 3), block 256, 8x4 warp tiles
// ---------------------------------------------------------------------------
__global__ __launch_bounds__(256, 7) void march_kernel(
        const float* __restrict__ poses) {
    int tid = threadIdx.x;
    int warp = tid >> 5, lane = tid & 31;
    int wx = warp & 3, wy = warp >> 2;
    int lx = lane & 7, ly = lane >> 3;
    int w = blockIdx.x * 32 + wx * 8 + lx;
    int h = blockIdx.y * 8 + wy * 4 + ly;
    int v = blockIdx.z;

    float ox, oy, oz, dx, dy, dz;
    ray_setup(poses, v, w, h, ox, oy, oz, dx, dy, dz);

    float t_exit = fminf(fminf(axis_exit(ox, dx), axis_exit(oy, dy)),
                         axis_exit(oz, dz));

    float t = 0.0f;
#pragma unroll 1
    for (int it = 0; it < NSTEP; ++it) {
        float cx = fminf(fmaxf(fmaf(t, dx, ox), 0.0f), CLAMP_HI);
        float cy = fminf(fmaxf(fmaf(t, dy, oy), 0.0f), CLAMP_HI);
        float cz = fminf(fmaxf(fmaf(t, dz, oz), 0.0f), CLAMP_HI);
        int x0 = (int)cx, y0 = (int)cy, z0 = (int)cz;
        float s = sdf_sample_h(x0, y0, z0,
                               cx - (float)x0, cy - (float)y0, cz - (float)z0);
        t = fmaf(fmaxf(s, 0.25f), 2.0f, t);
        if (__all_sync(0xffffffffu, t > t_exit)) break;
    }

    g_tbuf[(v * IMG_H + h) * IMG_W + w] = t;
}

// 3-level separable weights for resized-trilerp-of-source-trilerp along one axis
__device__ __forceinline__ void axis_w(int c0, float f, float* W, int* g) {
    float cc0 = (c0 * 95.0f) / 159.0f;
    int b0 = (int)cc0; float f0 = cc0 - (float)b0;
    float cc1 = ((c0 + 1) * 95.0f) / 159.0f;
    int b1 = (int)cc1; float f1 = cc1 - (float)b1;
    int l = b1 - b0;                    // 0 or 1
    float g0 = 1.0f - f;
    float wa = f * (1.0f - f1), wb = f * f1;
    W[0] = g0 * (1.0f - f0) + (l == 0 ? wa : 0.0f);
    W[1] = g0 * f0 + (l == 0 ? wb : wa);
    W[2] = (l == 0 ? 0.0f : wb);
    g[0] = b0;
    g[1] = min(b0 + 1, DG - 1);
    g[2] = min(b0 + 2, DG - 1);
}

__device__ __forceinline__ float gather27(const float* __restrict__ src,
                                          const int* gx, const int* gy, const int* gz,
                                          const float* Wx, const float* Wy, const float* Wz) {
    float acc = 0.0f;
#pragma unroll
    for (int ia = 0; ia < 3; ia++) {
        float accy = 0.0f;
#pragma unroll
        for (int ib = 0; ib < 3; ib++) {
            const float* rr = src + (gx[ia] * DG + gy[ib]) * DG;
            float accz = __ldg(rr + gz[0]) * Wz[0]
                       + __ldg(rr + gz[1]) * Wz[1]
                       + __ldg(rr + gz[2]) * Wz[2];
            accy = fmaf(Wy[ib], accz, accy);
        }
        acc = fmaf(Wx[ia], accy, acc);
    }
    return acc;
}

// ---------------------------------------------------------------------------
// Kernel 3: shade + loss. One thread per pixel; fused deterministic reduce.
// ---------------------------------------------------------------------------
__global__ __launch_bounds__(256) void shade_kernel(
        const float* __restrict__ rgb,
        const float* __restrict__ sem,
        const float* __restrict__ poses,
        const float* __restrict__ views,
        float* __restrict__ out) {
    int tid = threadIdx.x;
    int pix = blockIdx.x * 256 + tid;
    int v = pix / (IMG_H * IMG_W);
    int r = pix % (IMG_H * IMG_W);
    int h = r / IMG_W;
    int w = r % IMG_W;

    float ox, oy, oz, dx, dy, dz;
    ray_setup(poses, v, w, h, ox, oy, oz, dx, dy, dz);

    float t = g_tbuf[pix];
    float px = fmaf(t, dx, ox);
    float py = fmaf(t, dy, oy);
    float pz = fmaf(t, dz, oz);

    float cx = fminf(fmaxf(px, 0.0f), CLAMP_HI);
    float cy = fminf(fmaxf(py, 0.0f), CLAMP_HI);
    float cz = fminf(fmaxf(pz, 0.0f), CLAMP_HI);
    int x0 = (int)cx, y0 = (int)cy, z0 = (int)cz;
    float fx = cx - (float)x0, fy = cy - (float)y0, fz = cz - (float)z0;

    float s = sdf_sample_h(x0, y0, z0, fx, fy, fz);

    bool inside = (px >= 0.0f) && (px <= 159.0f)
               && (py >= 0.0f) && (py <= 159.0f)
               && (pz >= 0.0f) && (pz <= 159.0f);
    bool valid = inside && (fabsf(s) < 1.0f);

    float contrib = 0.0f;
    int cnt = 0;
    if (valid) {
        float Wx[3], Wy[3], Wz[3];
        int gx[3], gy[3], gz[3];
        axis_w(x0, fx, Wx, gx);
        axis_w(y0, fy, Wy, gy);
        axis_w(z0, fz, Wz, gz);

        float c0 = gather27(rgb,           gx, gy, gz, Wx, Wy, Wz);
        float c1 = gather27(rgb + DG3,     gx, gy, gz, Wx, Wy, Wz);
        float c2 = gather27(rgb + 2 * DG3, gx, gy, gz, Wx, Wy, Wz);

        int nx0 = min((int)(x0 * 0.6f), DG - 1);
        int nx1 = min((int)((x0 + 1) * 0.6f), DG - 1);
        int ny0 = min((int)(y0 * 0.6f), DG - 1);
        int ny1 = min((int)((y0 + 1) * 0.6f), DG - 1);
        int nz0 = min((int)(z0 * 0.6f), DG - 1);
        int nz1 = min((int)((z0 + 1) * 0.6f), DG - 1);
        float gxf = 1.0f - fx, gyf = 1.0f - fy, gzf = 1.0f - fz;
        const float* s00 = sem + (nx0 * DG + ny0) * DG;
        const float* s01 = sem + (nx0 * DG + ny1) * DG;
        const float* s10 = sem + (nx1 * DG + ny0) * DG;
        const float* s11 = sem + (nx1 * DG + ny1) * DG;
        float wv = gxf * gyf * (gzf * __ldg(s00 + nz0) + fz * __ldg(s00 + nz1))
                 + gxf * fy  * (gzf * __ldg(s01 + nz0) + fz * __ldg(s01 + nz1))
                 + fx  * gyf * (gzf * __ldg(s10 + nz0) + fz * __ldg(s10 + nz1))
                 + fx  * fy  * (gzf * __ldg(s11 + nz0) + fz * __ldg(s11 + nz1));

        const float* vw = views + (size_t)pix * 3;
        contrib = (fabsf(c0 - vw[0]) + fabsf(c1 - vw[1]) + fabsf(c2 - vw[2])) * wv;
        cnt = 1;
    }

    __shared__ float ssum[256];
    __shared__ int scnt[256];
    ssum[tid] = contrib;
    scnt[tid] = cnt;
    __syncthreads();
#pragma unroll
    for (int o = 128; o > 0; o >>= 1) {
        if (tid < o) {
            ssum[tid] += ssum[tid + o];
            scnt[tid] += scnt[tid + o];
        }
        __syncthreads();
    }
    __shared__ bool amLast;
    if (tid == 0) {
        g_psum[blockIdx.x] = ssum[0];
        g_pcnt[blockIdx.x] = scnt[0];
        __threadfence();
        int tk = atomicAdd(&g_count, 1);
        amLast = (tk == NBLK - 1);
    }
    __syncthreads();

    if (amLast) {
        float sacc = 0.0f; int cacc = 0;
        for (int k = tid; k < NBLK; k += 256) {
            sacc += g_psum[k];
            cacc += g_pcnt[k];
        }
        ssum[tid] = sacc;
        scnt[tid] = cacc;
        __syncthreads();
#pragma unroll
        for (int o = 128; o > 0; o >>= 1) {
            if (tid < o) {
                ssum[tid] += ssum[tid + o];
                scnt[tid] += scnt[tid + o];
            }
            __syncthreads();
        }
        if (tid == 0) {
            float nv = 3.0f * (float)scnt[0];
            out[0] = 8.0f * ssum[0] / fmaxf(nv, 1.0f);
            g_count = 0;
        }
    }
}

// ---------------------------------------------------------------------------
extern "C" void kernel_launch(void* const* d_in, const int* in_sizes, int n_in,
                              void* d_out, int out_size) {
    const float* sdf   = (const float*)d_in[0];
    const float* rgb   = (const float*)d_in[1];
    const float* sem   = (const float*)d_in[2];
    const float* poses = (const float*)d_in[3];
    const float* views = (const float*)d_in[4];

    dim3 rg(S, S / JPB);
    resize_sdf_kernel<<<rg, 256>>>(sdf);
    dim3 mg(IMG_W / 32, IMG_H / 8, NVIEW);
    march_kernel<<<mg, 256>>>(poses);
    shade_kernel<<<NBLK, 256>>>(rgb, sem, poses, views, (float*)d_out);
}

// round 16
// speedup vs baseline: 1.6437x; 1.0336x over previous
#include <cuda_runtime.h>
#include <cuda_fp16.h>

#define S 160
#define SS (S*S)
#define S3 (S*S*S)
#define DG 96
#define DG2 (DG*DG)
#define DG3 (DG*DG*DG)
#define IMG_H 240
#define IMG_W 320
#define NVIEW 3
#define NPIX (NVIEW*IMG_H*IMG_W)   // 230400
#define NSTEP 64
#define CLAMP_HI 158.999f          // f32(160 - 1.001)
#define NBLK 900
#define JPB 8                      // j-rows per resize block

// packed resized SDF, half precision, y-pair lanes:
//   g_sdfh[(x*S+y)*S+z] = float2 whose bits are two __half2:
//     .x bits = (S[y][z],   S[y+1][z])     (both y at z)
//     .y bits = (S[y][z+1], S[y+1][z+1])   (both y at z+1)
__device__ float2 g_sdfh[S3];      // 32 MB
__device__ float  g_tbuf[NPIX];    // final ray parameter t
__device__ float  g_psum[NBLK];
__device__ int    g_pcnt[NBLK];
__device__ int    g_count;         // zero-initialized; reset after use

union HF { __half2 h; float f; };

// ---------------------------------------------------------------------------
// Kernel 1: fat-block separable SDF resize with smem coefficient tables.
// grid (S, S/JPB), block 256.
// ---------------------------------------------------------------------------
__global__ __launch_bounds__(256) void resize_sdf_kernel(const float* __restrict__ sdf) {
    int i  = blockIdx.x;           // 0..159
    int j0 = blockIdx.y * JPB;     // 0,8,...,152
    int t  = threadIdx.x;          // 256

    __shared__ float ls[JPB + 1][DG];   // xy-bilerped rows j0..j0+JPB
    __shared__ float zfrac[S];          // fz per output z
    __shared__ int   zidx[S];           // z0 per output z
    __shared__ int   ybase[JPB + 1];    // (x0*DG+y0)*DG per row
    __shared__ int   ystep[JPB + 1];    // (y1-y0)*DG per row
    __shared__ float4 ywt[JPB + 1];     // bilerp weights per row
    __shared__ int   xstep;             // (x1-x0)*DG2

    // stage 0: coefficient tables (all divs happen once here)
    if (t < S) {
        float czf = (t * 95.0f) / 159.0f;   // identical expression as before
        int z0 = (int)czf;
        zidx[t]  = z0;
        zfrac[t] = czf - (float)z0;
    } else if (t < S + JPB + 1) {
        int jl = t - S;
        float cx = (i * 95.0f) / 159.0f;
        int x0 = (int)cx; float fx = cx - (float)x0; int x1 = min(x0 + 1, DG - 1);
        int jj = min(j0 + jl, S - 1);
        float cy = (jj * 95.0f) / 159.0f;
        int y0 = (int)cy; float fy = cy - (float)y0; int y1 = min(y0 + 1, DG - 1);
        float gxf = 1.0f - fx, gyf = 1.0f - fy;
        ybase[jl] = (x0 * DG + y0) * DG;
        ystep[jl] = (y1 - y0) * DG;
        ywt[jl] = make_float4(gxf * gyf, gxf * fy, fx * gyf, fx * fy);
        if (jl == 0) xstep = (x1 - x0) * DG2;
    }
    __syncthreads();

    // stage 1: xy-bilerp rows into smem (4 LDG + 4 FMA each)
    int xs = xstep;
    for (int q = t; q < (JPB + 1) * DG; q += 256) {
        int jl = q / DG, z = q - jl * DG;
        int base = ybase[jl] + z;
        int ys = ystep[jl];
        float4 wv = ywt[jl];
        ls[jl][z] = __ldg(sdf + base) * wv.x + __ldg(sdf + base + ys) * wv.y
                  + __ldg(sdf + base + xs) * wv.z + __ldg(sdf + base + xs + ys) * wv.w;
    }
    __syncthreads();

    // stage 2: z-lerp via tables + pack half4 (y-pair lanes)
    for (int o = t; o < JPB * S; o += 256) {
        int jl = o / S, z = o - jl * S;

        int z0 = zidx[z];           float fz = zfrac[z];
        int z1 = min(z0 + 1, DG - 1);
        int zb = min(z + 1, S - 1);
        int w0 = zidx[zb];          float fw = zfrac[zb];
        int w1 = min(w0 + 1, DG - 1);

        const float* A = ls[jl];
        const float* B = ls[jl + 1];
        float vA0 = fmaf(fz, A[z1] - A[z0], A[z0]) - 1.5f;   // y=j,   z
        float vA1 = fmaf(fw, A[w1] - A[w0], A[w0]) - 1.5f;   // y=j,   z+1
        float vB0 = fmaf(fz, B[z1] - B[z0], B[z0]) - 1.5f;   // y=j+1, z
        float vB1 = fmaf(fw, B[w1] - B[w0], B[w0]) - 1.5f;   // y=j+1, z+1

        HF lo, hi;
        lo.h = __floats2half2_rn(vA0, vB0);   // (y, y+1) at z
        hi.h = __floats2half2_rn(vA1, vB1);   // (y, y+1) at z+1
        g_sdfh[(i * S + (j0 + jl)) * S + z] = make_float2(lo.f, hi.f);
    }
}

// ---------------------------------------------------------------------------
// half2-vectorized SDF sample: 2x 8B loads; z-lerp in HFMA2 (both y lanes),
// then fp32 y and x lerps.
// ---------------------------------------------------------------------------
__device__ __forceinline__ float sdf_sample_h(int x0, int y0, int z0,
                                              float fx, float fy, float fz) {
    const float2* p = g_sdfh + ((x0 * S + y0) * S + z0);
    float2 A = __ldg(p);           // x0 plane
    float2 B = __ldg(p + SS);      // x1 plane
    __half2 fz2 = __float2half2_rn(fz);
    HF alo, ahi, blo, bhi;
    alo.f = A.x; ahi.f = A.y;
    blo.f = B.x; bhi.f = B.y;
    __half2 vzA = __hfma2(fz2, __hsub2(ahi.h, alo.h), alo.h);  // (vA[y], vA[y+1])
    __half2 vzB = __hfma2(fz2, __hsub2(bhi.h, blo.h), blo.h);  // (vB[y], vB[y+1])
    float2 a = __half22float2(vzA);
    float2 b = __half22float2(vzB);
    float vA = fmaf(fy, a.y - a.x, a.x);
    float vB = fmaf(fy, b.y - b.x, b.x);
    return fmaf(fx, vB - vA, vA);
}

// shared ray setup
__device__ __forceinline__ void ray_setup(const float* __restrict__ poses,
                                          int v, int w, int h,
                                          float& ox, float& oy, float& oz,
                                          float& dx, float& dy, float& dz) {
    const float offx[3] = {0.0f, 36.0f, 40.0f};
    const float offz[3] = {0.0f, 44.0f, 23.0f};
    const float* M = poses + v * 16;
    ox = M[3]  / 0.0301f + offx[v];
    oy = M[7]  / 0.0301f;
    oz = M[11] / 0.0301f + offz[v];
    float uu = ((float)w - 160.0f) / 277.0f;
    float vv = ((float)h - 120.0f) / 277.0f;
    dx = M[0] * uu + M[1] * vv + M[2];
    dy = M[4] * uu + M[5] * vv + M[6];
    dz = M[8] * uu + M[9] * vv + M[10];
    float nrm = sqrtf(dx * dx + dy * dy + dz * dz);
    dx /= nrm; dy /= nrm; dz /= nrm;
}

// exit time through the far plane along one axis
__device__ __forceinline__ float axis_exit(float o, float d) {
    if (d > 0.0f) return (159.0f - o) / d;
    if (d < 0.0f) return -o / d;
    return (o >= 0.0f && o <= 159.0f) ? 3.0e38f : -1.0f;
}

// ---------------------------------------------------------------------------
// Kernel 2: branch-free ray march -> write t. Single wave (7 blocks/SM).
// grid (10, 30, 3), block 256, 8x4 warp tiles
// ---------------------------------------------------------------------------
__global__ __launch_bounds__(256, 7) void march_kernel(
        const float* __restrict__ poses) {
    int tid = threadIdx.x;
    int warp = tid >> 5, lane = tid & 31;
    int wx = warp & 3, wy = warp >> 2;
    int lx = lane & 7, ly = lane >> 3;
    int w = blockIdx.x * 32 + wx * 8 + lx;
    int h = blockIdx.y * 8 + wy * 4 + ly;
    int v = blockIdx.z;

    float ox, oy, oz, dx, dy, dz;
    ray_setup(poses, v, w, h, ox, oy, oz, dx, dy, dz);

    float t_exit = fminf(fminf(axis_exit(ox, dx), axis_exit(oy, dy)),
                         axis_exit(oz, dz));

    float t = 0.0f;
#pragma unroll 1
    for (int it = 0; it < NSTEP; ++it) {
        float cx = fminf(fmaxf(fmaf(t, dx, ox), 0.0f), CLAMP_HI);
        float cy = fminf(fmaxf(fmaf(t, dy, oy), 0.0f), CLAMP_HI);
        float cz = fminf(fmaxf(fmaf(t, dz, oz), 0.0f), CLAMP_HI);
        int x0 = (int)cx, y0 = (int)cy, z0 = (int)cz;
        float s = sdf_sample_h(x0, y0, z0,
                               cx - (float)x0, cy - (float)y0, cz - (float)z0);
        t = fmaf(fmaxf(s, 0.25f), 2.0f, t);
        if (__all_sync(0xffffffffu, t > t_exit)) break;
    }

    g_tbuf[(v * IMG_H + h) * IMG_W + w] = t;
}

// 3-level separable weights for resized-trilerp-of-source-trilerp along one axis
__device__ __forceinline__ void axis_w(int c0, float f, float* W, int* g) {
    float cc0 = (c0 * 95.0f) / 159.0f;
    int b0 = (int)cc0; float f0 = cc0 - (float)b0;
    float cc1 = ((c0 + 1) * 95.0f) / 159.0f;
    int b1 = (int)cc1; float f1 = cc1 - (float)b1;
    int l = b1 - b0;                    // 0 or 1
    float g0 = 1.0f - f;
    float wa = f * (1.0f - f1), wb = f * f1;
    W[0] = g0 * (1.0f - f0) + (l == 0 ? wa : 0.0f);
    W[1] = g0 * f0 + (l == 0 ? wb : wa);
    W[2] = (l == 0 ? 0.0f : wb);
    g[0] = b0;
    g[1] = min(b0 + 1, DG - 1);
    g[2] = min(b0 + 2, DG - 1);
}

__device__ __forceinline__ float gather27(const float* __restrict__ src,
                                          const int* gx, const int* gy, const int* gz,
                                          const float* Wx, const float* Wy, const float* Wz) {
    float acc = 0.0f;
#pragma unroll
    for (int ia = 0; ia < 3; ia++) {
        float accy = 0.0f;
#pragma unroll
        for (int ib = 0; ib < 3; ib++) {
            const float* rr = src + (gx[ia] * DG + gy[ib]) * DG;
            float accz = __ldg(rr + gz[0]) * Wz[0]
                       + __ldg(rr + gz[1]) * Wz[1]
                       + __ldg(rr + gz[2]) * Wz[2];
            accy = fmaf(Wy[ib], accz, accy);
        }
        acc = fmaf(Wx[ia], accy, acc);
    }
    return acc;
}

// ---------------------------------------------------------------------------
// Kernel 3: shade + loss. One thread per pixel; fused deterministic reduce.
// ---------------------------------------------------------------------------
__global__ __launch_bounds__(256) void shade_kernel(
        const float* __restrict__ rgb,
        const float* __restrict__ sem,
        const float* __restrict__ poses,
        const float* __restrict__ views,
        float* __restrict__ out) {
    int tid = threadIdx.x;
    int pix = blockIdx.x * 256 + tid;
    int v = pix / (IMG_H * IMG_W);
    int r = pix % (IMG_H * IMG_W);
    int h = r / IMG_W;
    int w = r % IMG_W;

    float ox, oy, oz, dx, dy, dz;
    ray_setup(poses, v, w, h, ox, oy, oz, dx, dy, dz);

    float t = g_tbuf[pix];
    float px = fmaf(t, dx, ox);
    float py = fmaf(t, dy, oy);
    float pz = fmaf(t, dz, oz);

    float cx = fminf(fmaxf(px, 0.0f), CLAMP_HI);
    float cy = fminf(fmaxf(py, 0.0f), CLAMP_HI);
    float cz = fminf(fmaxf(pz, 0.0f), CLAMP_HI);
    int x0 = (int)cx, y0 = (int)cy, z0 = (int)cz;
    float fx = cx - (float)x0, fy = cy - (float)y0, fz = cz - (float)z0;

    float s = sdf_sample_h(x0, y0, z0, fx, fy, fz);

    bool inside = (px >= 0.0f) && (px <= 159.0f)
               && (py >= 0.0f) && (py <= 159.0f)
               && (pz >= 0.0f) && (pz <= 159.0f);
    bool valid = inside && (fabsf(s) < 1.0f);

    float contrib = 0.0f;
    int cnt = 0;
    if (valid) {
        float Wx[3], Wy[3], Wz[3];
        int gx[3], gy[3], gz[3];
        axis_w(x0, fx, Wx, gx);
        axis_w(y0, fy, Wy, gy);
        axis_w(z0, fz, Wz, gz);

        float c0 = gather27(rgb,           gx, gy, gz, Wx, Wy, Wz);
        float c1 = gather27(rgb + DG3,     gx, gy, gz, Wx, Wy, Wz);
        float c2 = gather27(rgb + 2 * DG3, gx, gy, gz, Wx, Wy, Wz);

        int nx0 = min((int)(x0 * 0.6f), DG - 1);
        int nx1 = min((int)((x0 + 1) * 0.6f), DG - 1);
        int ny0 = min((int)(y0 * 0.6f), DG - 1);
        int ny1 = min((int)((y0 + 1) * 0.6f), DG - 1);
        int nz0 = min((int)(z0 * 0.6f), DG - 1);
        int nz1 = min((int)((z0 + 1) * 0.6f), DG - 1);
        float gxf = 1.0f - fx, gyf = 1.0f - fy, gzf = 1.0f - fz;
        const float* s00 = sem + (nx0 * DG + ny0) * DG;
        const float* s01 = sem + (nx0 * DG + ny1) * DG;
        const float* s10 = sem + (nx1 * DG + ny0) * DG;
        const float* s11 = sem + (nx1 * DG + ny1) * DG;
        float wv = gxf * gyf * (gzf * __ldg(s00 + nz0) + fz * __ldg(s00 + nz1))
                 + gxf * fy  * (gzf * __ldg(s01 + nz0) + fz * __ldg(s01 + nz1))
                 + fx  * gyf * (gzf * __ldg(s10 + nz0) + fz * __ldg(s10 + nz1))
                 + fx  * fy  * (gzf * __ldg(s11 + nz0) + fz * __ldg(s11 + nz1));

        const float* vw = views + (size_t)pix * 3;
        contrib = (fabsf(c0 - vw[0]) + fabsf(c1 - vw[1]) + fabsf(c2 - vw[2])) * wv;
        cnt = 1;
    }

    __shared__ float ssum[256];
    __shared__ int scnt[256];
    ssum[tid] = contrib;
    scnt[tid] = cnt;
    __syncthreads();
#pragma unroll
    for (int o = 128; o > 0; o >>= 1) {
        if (tid < o) {
            ssum[tid] += ssum[tid + o];
            scnt[tid] += scnt[tid + o];
        }
        __syncthreads();
    }
    __shared__ bool amLast;
    if (tid == 0) {
        g_psum[blockIdx.x] = ssum[0];
        g_pcnt[blockIdx.x] = scnt[0];
        __threadfence();
        int tk = atomicAdd(&g_count, 1);
        amLast = (tk == NBLK - 1);
    }
    __syncthreads();

    if (amLast) {
        float sacc = 0.0f; int cacc = 0;
        for (int k = tid; k < NBLK; k += 256) {
            sacc += g_psum[k];
            cacc += g_pcnt[k];
        }
        ssum[tid] = sacc;
        scnt[tid] = cacc;
        __syncthreads();
#pragma unroll
        for (int o = 128; o > 0; o >>= 1) {
            if (tid < o) {
                ssum[tid] += ssum[tid + o];
                scnt[tid] += scnt[tid + o];
            }
            __syncthreads();
        }
        if (tid == 0) {
            float nv = 3.0f * (float)scnt[0];
            out[0] = 8.0f * ssum[0] / fmaxf(nv, 1.0f);
            g_count = 0;
        }
    }
}

// ---------------------------------------------------------------------------
extern "C" void kernel_launch(void* const* d_in, const int* in_sizes, int n_in,
                              void* d_out, int out_size) {
    const float* sdf   = (const float*)d_in[0];
    const float* rgb   = (const float*)d_in[1];
    const float* sem   = (const float*)d_in[2];
    const float* poses = (const float*)d_in[3];
    const float* views = (const float*)d_in[4];

    dim3 rg(S, S / JPB);
    resize_sdf_kernel<<<rg, 256>>>(sdf);
    dim3 mg(IMG_W / 32, IMG_H / 8, NVIEW);
    march_kernel<<<mg, 256>>>(poses);
    shade_kernel<<<NBLK, 256>>>(rgb, sem, poses, views, (float*)d_out);
}